// round 10
// baseline (speedup 1.0000x reference)
#include <cuda_runtime.h>

// FISTA box-QP denoiser, two passes of 100 iters.
// Fused 5-point D^T D stencil (exact via linear-extrapolated ghosts).
// TWO ROWS PER LANE packed into f32x2; rolling old-value registers for
// the in-place stencil. R10: scalar-broadcast constants + launch_bounds
// (128,4) to fit 128 regs -> 16 warps/SM (was 12).

#define NCOL 512
#define REG  16
#define NITER 100

// ---- packed f32x2 helpers (sm_103a) ----
__device__ __forceinline__ float2 f2add(float2 a, float2 b) {
    float2 r;
    asm("{\n\t.reg .b64 A,B,R;\n\t"
        "mov.b64 A,{%2,%3};\n\tmov.b64 B,{%4,%5};\n\t"
        "add.rn.f32x2 R,A,B;\n\t"
        "mov.b64 {%0,%1},R;\n\t}"
        : "=f"(r.x), "=f"(r.y)
        : "f"(a.x), "f"(a.y), "f"(b.x), "f"(b.y));
    return r;
}
// r = a * broadcast(s)
__device__ __forceinline__ float2 f2mul_s(float2 a, float s) {
    float2 r;
    asm("{\n\t.reg .b64 A,B,R;\n\t"
        "mov.b64 A,{%2,%3};\n\tmov.b64 B,{%4,%4};\n\t"
        "mul.rn.f32x2 R,A,B;\n\t"
        "mov.b64 {%0,%1},R;\n\t}"
        : "=f"(r.x), "=f"(r.y)
        : "f"(a.x), "f"(a.y), "f"(s));
    return r;
}
// r = a * broadcast(s) + c
__device__ __forceinline__ float2 f2fma_s(float2 a, float s, float2 c) {
    float2 r;
    asm("{\n\t.reg .b64 A,B,C,R;\n\t"
        "mov.b64 A,{%2,%3};\n\tmov.b64 B,{%4,%4};\n\tmov.b64 C,{%5,%6};\n\t"
        "fma.rn.f32x2 R,A,B,C;\n\t"
        "mov.b64 {%0,%1},R;\n\t}"
        : "=f"(r.x), "=f"(r.y)
        : "f"(a.x), "f"(a.y), "f"(s), "f"(c.x), "f"(c.y));
    return r;
}

__device__ __forceinline__ float2 shup2(float2 v) {
    float2 r;
    r.x = __shfl_up_sync(0xffffffffu, v.x, 1);
    r.y = __shfl_up_sync(0xffffffffu, v.y, 1);
    return r;
}
__device__ __forceinline__ float2 shdn2(float2 v) {
    float2 r;
    r.x = __shfl_down_sync(0xffffffffu, v.x, 1);
    r.y = __shfl_down_sync(0xffffffffu, v.y, 1);
    return r;
}

__global__ void __launch_bounds__(128, 4)
denoise_fista2(const float* __restrict__ in, float* __restrict__ out, int nrows)
{
    const int gwarp = (int)((blockIdx.x * blockDim.x + threadIdx.x) >> 5);
    const int lane  = (int)(threadIdx.x & 31);
    const int r0 = 2 * gwarp;
    if (r0 >= nrows) return;

    const float LAM  = 10.0f;
    const float step = 1.0f / (2.0f * (1.0f + 16.0f * LAM));
    // v = Ac*z + Bc*y + Cc*s1 + Dc*s2,  s1=z[i-2]+z[i+2], s2=z[i-1]+z[i+1]
    const float Ac = 1.0f - 2.0f * step - 12.0f * step * LAM;
    const float Bc = 2.0f * step;
    const float Cc = -2.0f * step * LAM;
    const float Dc = 8.0f * step * LAM;

    const float* __restrict__ sa = in  + (size_t)r0 * NCOL + lane * REG;
    const float* __restrict__ sb = sa + NCOL;
    float*       __restrict__ da = out + (size_t)r0 * NCOL + lane * REG;
    float*       __restrict__ db = da + NCOL;

    float2 y[REG], x[REG], z[REG];
#pragma unroll
    for (int q = 0; q < REG / 4; q++) {
        float4 va = *reinterpret_cast<const float4*>(sa + 4 * q);
        float4 vb = *reinterpret_cast<const float4*>(sb + 4 * q);
        y[4*q+0] = make_float2(va.x, vb.x);
        y[4*q+1] = make_float2(va.y, vb.y);
        y[4*q+2] = make_float2(va.z, vb.z);
        y[4*q+3] = make_float2(va.w, vb.w);
    }

#pragma unroll 1
    for (int pass = 0; pass < 2; pass++) {
        // x0 = proj(y) = clip(y, 0, y); z0 = x0; t = 1
#pragma unroll
        for (int j = 0; j < REG; j++) {
            float2 p;
            p.x = fminf(fmaxf(y[j].x, 0.0f), y[j].x);
            p.y = fminf(fmaxf(y[j].y, 0.0f), y[j].y);
            x[j] = p; z[j] = p;
        }
        float t = 1.0f;

#pragma unroll 1
        for (int k = 0; k < NITER; k++) {
            // halos (all from OLD z): z[gi-1], z[gi-2], z[gi+16], z[gi+17]
            float2 zu1 = shup2(z[REG - 1]);
            float2 zu2 = shup2(z[REG - 2]);
            float2 zd1 = shdn2(z[0]);
            float2 zd2 = shdn2(z[1]);

            // ghost extrapolation at the two global ends:
            //   left:  z[-1] = 2 z0 - z1,   z[-2] = 2 z[-1] - z0
            //   right: z[n]  = 2 z[n-1] - z[n-2],  z[n+1] = 2 z[n] - z[n-1]
            {
                float2 e1 = f2fma_s(z[1], -1.0f, f2add(z[0], z[0]));
                float2 e2 = f2fma_s(z[0], -1.0f, f2add(e1, e1));
                if (lane == 0) { zu1 = e1; zu2 = e2; }
                float2 f1  = f2fma_s(z[REG - 2], -1.0f, f2add(z[REG - 1], z[REG - 1]));
                float2 f2v = f2fma_s(z[REG - 1], -1.0f, f2add(f1, f1));
                if (lane == 31) { zd1 = f1; zd2 = f2v; }
            }

            // momentum scalar (uniform across lanes & rows)
            float tn = 0.5f * (1.0f + sqrtf(1.0f + 4.0f * t * t));
            float c  = __fdividef(t - 1.0f, tn);
            t = tn;

            // rolling OLD backward neighbors (in-place stencil hazard fix)
            float2 zm2 = zu2;
            float2 zm1 = zu1;

#pragma unroll
            for (int j = 0; j < REG; j++) {
                float2 np1 = (j <= REG - 2) ? z[j + 1] : zd1;
                float2 np2 = (j <= REG - 3) ? z[j + 2] : ((j == REG - 2) ? zd1 : zd2);

                float2 zc = z[j];                          // old center
                float2 s1 = f2add(zm2, np2);
                float2 s2 = f2add(zm1, np1);
                float2 w  = f2fma_s(s2, Dc, f2mul_s(s1, Cc));
                float2 v  = f2fma_s(zc, Ac, f2fma_s(y[j], Bc, w));

                float2 xn;
                xn.x = fminf(fmaxf(v.x, 0.0f), y[j].x);
                xn.y = fminf(fmaxf(v.y, 0.0f), y[j].y);

                float2 dz = f2fma_s(x[j], -1.0f, xn);      // xn - x
                zm2 = zm1;                                 // roll OLD values
                zm1 = zc;
                z[j] = f2fma_s(dz, c, xn);                 // xn + c*(xn-x)
                x[j] = xn;
            }
        }

        if (pass == 0) {
#pragma unroll
            for (int j = 0; j < REG; j++) y[j] = x[j];
        }
    }

#pragma unroll
    for (int q = 0; q < REG / 4; q++) {
        float4 va = make_float4(x[4*q+0].x, x[4*q+1].x, x[4*q+2].x, x[4*q+3].x);
        float4 vb = make_float4(x[4*q+0].y, x[4*q+1].y, x[4*q+2].y, x[4*q+3].y);
        *reinterpret_cast<float4*>(da + 4 * q) = va;
        *reinterpret_cast<float4*>(db + 4 * q) = vb;
    }
}

extern "C" void kernel_launch(void* const* d_in, const int* in_sizes, int n_in,
                              void* d_out, int out_size)
{
    const float* in = (const float*)d_in[0];
    float* out = (float*)d_out;
    const int nrows = in_sizes[0] / NCOL;             // 16384 rows
    const int nwarps = nrows / 2;                     // 2 rows per warp
    const int warps_per_block = 4;
    const int threads = warps_per_block * 32;         // 128
    const int blocks = (nwarps + warps_per_block - 1) / warps_per_block;
    denoise_fista2<<<blocks, threads>>>(in, out, nrows);
}

// round 11
// speedup vs baseline: 1.6168x; 1.6168x over previous
#include <cuda_runtime.h>

// FISTA box-QP denoiser, two passes of 100 iters.
// Fused 5-point D^T D stencil (exact via linear-extrapolated ghosts).
// TWO ROWS PER LANE packed into f32x2; rolling old-value registers for
// the in-place stencil. R11: y lives in lane-private SMEM slots (-32 regs)
// so (128,4) fits WITHOUT spilling -> 16 warps/SM.

#define NCOL 512
#define REG  16
#define NITER 100
#define WPB  4    // warps per block

// ---- packed f32x2 helpers (sm_103a) ----
__device__ __forceinline__ float2 f2add(float2 a, float2 b) {
    float2 r;
    asm("{\n\t.reg .b64 A,B,R;\n\t"
        "mov.b64 A,{%2,%3};\n\tmov.b64 B,{%4,%5};\n\t"
        "add.rn.f32x2 R,A,B;\n\t"
        "mov.b64 {%0,%1},R;\n\t}"
        : "=f"(r.x), "=f"(r.y)
        : "f"(a.x), "f"(a.y), "f"(b.x), "f"(b.y));
    return r;
}
// r = a * broadcast(s)
__device__ __forceinline__ float2 f2mul_s(float2 a, float s) {
    float2 r;
    asm("{\n\t.reg .b64 A,B,R;\n\t"
        "mov.b64 A,{%2,%3};\n\tmov.b64 B,{%4,%4};\n\t"
        "mul.rn.f32x2 R,A,B;\n\t"
        "mov.b64 {%0,%1},R;\n\t}"
        : "=f"(r.x), "=f"(r.y)
        : "f"(a.x), "f"(a.y), "f"(s));
    return r;
}
// r = a * broadcast(s) + c
__device__ __forceinline__ float2 f2fma_s(float2 a, float s, float2 c) {
    float2 r;
    asm("{\n\t.reg .b64 A,B,C,R;\n\t"
        "mov.b64 A,{%2,%3};\n\tmov.b64 B,{%4,%4};\n\tmov.b64 C,{%5,%6};\n\t"
        "fma.rn.f32x2 R,A,B,C;\n\t"
        "mov.b64 {%0,%1},R;\n\t}"
        : "=f"(r.x), "=f"(r.y)
        : "f"(a.x), "f"(a.y), "f"(s), "f"(c.x), "f"(c.y));
    return r;
}

__device__ __forceinline__ float2 shup2(float2 v) {
    float2 r;
    r.x = __shfl_up_sync(0xffffffffu, v.x, 1);
    r.y = __shfl_up_sync(0xffffffffu, v.y, 1);
    return r;
}
__device__ __forceinline__ float2 shdn2(float2 v) {
    float2 r;
    r.x = __shfl_down_sync(0xffffffffu, v.x, 1);
    r.y = __shfl_down_sync(0xffffffffu, v.y, 1);
    return r;
}

__global__ void __launch_bounds__(128, 4)
denoise_fista2(const float* __restrict__ in, float* __restrict__ out, int nrows)
{
    // y storage: lane-private slot per (warp, j, lane). 8B lane stride is
    // conflict-free for LDS.64 (half-warp phases). 16 KB per block.
    __shared__ float2 ysm[WPB][REG][32];

    const int gwarp = (int)((blockIdx.x * blockDim.x + threadIdx.x) >> 5);
    const int wib   = (int)(threadIdx.x >> 5);
    const int lane  = (int)(threadIdx.x & 31);
    const int r0 = 2 * gwarp;
    if (r0 >= nrows) return;

    const float LAM  = 10.0f;
    const float step = 1.0f / (2.0f * (1.0f + 16.0f * LAM));
    // v = Ac*z + Bc*y + Cc*s1 + Dc*s2,  s1=z[i-2]+z[i+2], s2=z[i-1]+z[i+1]
    const float Ac = 1.0f - 2.0f * step - 12.0f * step * LAM;
    const float Bc = 2.0f * step;
    const float Cc = -2.0f * step * LAM;
    const float Dc = 8.0f * step * LAM;

    const float* __restrict__ sa = in  + (size_t)r0 * NCOL + lane * REG;
    const float* __restrict__ sb = sa + NCOL;

    float2 x[REG], z[REG];
    // load + pass-0 init:  x0 = proj(y) = clip(y, 0, y); z0 = x0; y -> smem
#pragma unroll
    for (int q = 0; q < REG / 4; q++) {
        float4 va = *reinterpret_cast<const float4*>(sa + 4 * q);
        float4 vb = *reinterpret_cast<const float4*>(sb + 4 * q);
        float2 p0 = make_float2(va.x, vb.x);
        float2 p1 = make_float2(va.y, vb.y);
        float2 p2 = make_float2(va.z, vb.z);
        float2 p3 = make_float2(va.w, vb.w);
        ysm[wib][4*q+0][lane] = p0;
        ysm[wib][4*q+1][lane] = p1;
        ysm[wib][4*q+2][lane] = p2;
        ysm[wib][4*q+3][lane] = p3;
        float2 t0, t1, t2, t3;
        t0.x = fminf(fmaxf(p0.x, 0.0f), p0.x); t0.y = fminf(fmaxf(p0.y, 0.0f), p0.y);
        t1.x = fminf(fmaxf(p1.x, 0.0f), p1.x); t1.y = fminf(fmaxf(p1.y, 0.0f), p1.y);
        t2.x = fminf(fmaxf(p2.x, 0.0f), p2.x); t2.y = fminf(fmaxf(p2.y, 0.0f), p2.y);
        t3.x = fminf(fmaxf(p3.x, 0.0f), p3.x); t3.y = fminf(fmaxf(p3.y, 0.0f), p3.y);
        x[4*q+0] = t0; z[4*q+0] = t0;
        x[4*q+1] = t1; z[4*q+1] = t1;
        x[4*q+2] = t2; z[4*q+2] = t2;
        x[4*q+3] = t3; z[4*q+3] = t3;
    }

#pragma unroll 1
    for (int pass = 0; pass < 2; pass++) {
        float t = 1.0f;

#pragma unroll 1
        for (int k = 0; k < NITER; k++) {
            // halos (all from OLD z): z[gi-1], z[gi-2], z[gi+16], z[gi+17]
            float2 zu1 = shup2(z[REG - 1]);
            float2 zu2 = shup2(z[REG - 2]);
            float2 zd1 = shdn2(z[0]);
            float2 zd2 = shdn2(z[1]);

            // ghost extrapolation at the two global ends:
            //   left:  z[-1] = 2 z0 - z1,   z[-2] = 2 z[-1] - z0
            //   right: z[n]  = 2 z[n-1] - z[n-2],  z[n+1] = 2 z[n] - z[n-1]
            {
                float2 e1 = f2fma_s(z[1], -1.0f, f2add(z[0], z[0]));
                float2 e2 = f2fma_s(z[0], -1.0f, f2add(e1, e1));
                if (lane == 0) { zu1 = e1; zu2 = e2; }
                float2 f1  = f2fma_s(z[REG - 2], -1.0f, f2add(z[REG - 1], z[REG - 1]));
                float2 f2v = f2fma_s(z[REG - 1], -1.0f, f2add(f1, f1));
                if (lane == 31) { zd1 = f1; zd2 = f2v; }
            }

            // momentum scalar (uniform across lanes & rows)
            float tn = 0.5f * (1.0f + sqrtf(1.0f + 4.0f * t * t));
            float c  = __fdividef(t - 1.0f, tn);
            t = tn;

            // rolling OLD backward neighbors (in-place stencil hazard fix)
            float2 zm2 = zu2;
            float2 zm1 = zu1;

#pragma unroll
            for (int j = 0; j < REG; j++) {
                float2 np1 = (j <= REG - 2) ? z[j + 1] : zd1;
                float2 np2 = (j <= REG - 3) ? z[j + 2] : ((j == REG - 2) ? zd1 : zd2);

                float2 yj = ysm[wib][j][lane];             // LDS.64, lane-private
                float2 zc = z[j];                          // old center
                float2 s1 = f2add(zm2, np2);
                float2 s2 = f2add(zm1, np1);
                float2 w  = f2fma_s(s2, Dc, f2mul_s(s1, Cc));
                float2 v  = f2fma_s(zc, Ac, f2fma_s(yj, Bc, w));

                float2 xn;
                xn.x = fminf(fmaxf(v.x, 0.0f), yj.x);
                xn.y = fminf(fmaxf(v.y, 0.0f), yj.y);

                float2 dz = f2fma_s(x[j], -1.0f, xn);      // xn - x
                zm2 = zm1;                                 // roll OLD values
                zm1 = zc;
                z[j] = f2fma_s(dz, c, xn);                 // xn + c*(xn-x)
                x[j] = xn;
            }
        }

        if (pass == 0) {
            // y(pass2) = x; proj(y)=y since x>=0, so x0=x, z0=x.
            // Slots are lane-private -> no sync needed.
#pragma unroll
            for (int j = 0; j < REG; j++) {
                ysm[wib][j][lane] = x[j];
                z[j] = x[j];
            }
        }
    }

    float* __restrict__ da = out + (size_t)r0 * NCOL + lane * REG;
    float* __restrict__ db = da + NCOL;
#pragma unroll
    for (int q = 0; q < REG / 4; q++) {
        float4 va = make_float4(x[4*q+0].x, x[4*q+1].x, x[4*q+2].x, x[4*q+3].x);
        float4 vb = make_float4(x[4*q+0].y, x[4*q+1].y, x[4*q+2].y, x[4*q+3].y);
        *reinterpret_cast<float4*>(da + 4 * q) = va;
        *reinterpret_cast<float4*>(db + 4 * q) = vb;
    }
}

extern "C" void kernel_launch(void* const* d_in, const int* in_sizes, int n_in,
                              void* d_out, int out_size)
{
    const float* in = (const float*)d_in[0];
    float* out = (float*)d_out;
    const int nrows = in_sizes[0] / NCOL;             // 16384 rows
    const int nwarps = nrows / 2;                     // 2 rows per warp
    const int threads = WPB * 32;                     // 128
    const int blocks = (nwarps + WPB - 1) / WPB;
    denoise_fista2<<<blocks, threads>>>(in, out, nrows);
}